// round 1
// baseline (speedup 1.0000x reference)
#include <cuda_runtime.h>

// Problem constants (fixed-shape problem)
#define DIMD 272          // capsule feature dim
#define NC   19           // num classes
#define NROWS 65536       // B*H*Wd = 8*64*128
#define ROWS_PER_BLOCK 256
#define THREADS_GEMM 128
#define DCHUNK 34         // 272 = 8 * 34
#define NCHUNKS 8
#define XS_STRIDE 35      // 35 mod 32 = 3 (odd) -> conflict-free column reads
#define GROUPS 6          // reduction groups in segment kernel (6*19 = 114 <= 128)

// Scratch: projected features Z = X @ W  (65536 x 19 fp32 = ~5 MB, L2-resident)
__device__ float g_Z[(size_t)NROWS * NC];

// ---------------------------------------------------------------------------
// Kernel 1: Z[r][c] = sum_d X[r][d] * W[d][c]      (no bias here)
// Register tile: each thread computes 2 rows x 19 cols.
// ---------------------------------------------------------------------------
__global__ __launch_bounds__(THREADS_GEMM)
void proj_kernel(const float* __restrict__ X, const float* __restrict__ W) {
    __shared__ float ws[DIMD * NC];                     // 20672 B (full W)
    __shared__ float xs[ROWS_PER_BLOCK * XS_STRIDE];    // 35840 B (X chunk)

    const int t = threadIdx.x;
    const int row0 = blockIdx.x * ROWS_PER_BLOCK;

    // Stage full W into shared (coalesced)
    for (int i = t; i < DIMD * NC; i += THREADS_GEMM)
        ws[i] = W[i];

    float acc0[NC], acc1[NC];
#pragma unroll
    for (int c = 0; c < NC; c++) { acc0[c] = 0.f; acc1[c] = 0.f; }

    for (int ch = 0; ch < NCHUNKS; ch++) {
        __syncthreads();   // protects xs reuse (and ws on first iter)
        // Stage X chunk: rows [row0, row0+256), d in [ch*34, ch*34+34)
        for (int i = t; i < ROWS_PER_BLOCK * DCHUNK; i += THREADS_GEMM) {
            int r  = i / DCHUNK;
            int dd = i - r * DCHUNK;
            xs[r * XS_STRIDE + dd] =
                X[(size_t)(row0 + r) * DIMD + ch * DCHUNK + dd];
        }
        __syncthreads();

        const float* wp = &ws[ch * DCHUNK * NC];
#pragma unroll 2
        for (int dd = 0; dd < DCHUNK; dd++) {
            // rows t and t+128: lane stride 35 floats -> conflict-free
            float xa = xs[t * XS_STRIDE + dd];
            float xb = xs[(t + 128) * XS_STRIDE + dd];
#pragma unroll
            for (int c = 0; c < NC; c++) {
                float w = wp[dd * NC + c];   // broadcast LDS
                acc0[c] = fmaf(xa, w, acc0[c]);
                acc1[c] = fmaf(xb, w, acc1[c]);
            }
        }
    }

    const size_t ra = (size_t)(row0 + t) * NC;
    const size_t rb = (size_t)(row0 + t + 128) * NC;
#pragma unroll
    for (int c = 0; c < NC; c++) {
        g_Z[ra + c] = acc0[c];
        g_Z[rb + c] = acc1[c];
    }
}

// ---------------------------------------------------------------------------
// Kernel 2: one block per segment. segment_ids are sorted, so binary-search
// the [start,end) range, sum Z rows (19 cols), then /count + bias -> sigmoid.
// ---------------------------------------------------------------------------
__global__ __launch_bounds__(128)
void seg_kernel(const int* __restrict__ pidx, const int* __restrict__ segs,
                const float* __restrict__ bias, float* __restrict__ out, int P) {
    const int s = blockIdx.x;
    const int t = threadIdx.x;

    // lower_bound(segs, s) and upper_bound(segs, s) — all threads identical
    int lo = 0, hi = P;
    while (lo < hi) { int mid = (lo + hi) >> 1; if (segs[mid] < s) lo = mid + 1; else hi = mid; }
    const int start = lo;
    hi = P;
    while (lo < hi) { int mid = (lo + hi) >> 1; if (segs[mid] <= s) lo = mid + 1; else hi = mid; }
    const int end = lo;

    __shared__ float sAcc[GROUPS * NC];

    if (t < GROUPS * NC) {
        const int g = t / NC;
        const int c = t - g * NC;
        float acc = 0.f;
        for (int p = start + g; p < end; p += GROUPS) {
            int r = pidx[p];                       // broadcast within group
            acc += g_Z[(size_t)r * NC + c];        // 19-wide coalesced-ish
        }
        sAcc[t] = acc;
    }
    __syncthreads();

    if (t < NC) {
        float sum = 0.f;
#pragma unroll
        for (int g = 0; g < GROUPS; g++) sum += sAcc[g * NC + t];
        float cnt = (float)(end - start);
        float pooled = sum / fmaxf(cnt, 1.0f);
        float x = pooled + bias[t];
        out[(size_t)s * NC + t] = 1.0f / (1.0f + __expf(-x));
    }
}

// ---------------------------------------------------------------------------
// Launch. Inputs (metadata order):
//   0 class_capsules f32 [8,64,128,272]   1 W f32 [272,19]   2 b f32 [19]
//   3 point_idx i32 [524288]              4 segment_ids i32 [524288] (sorted)
//   5 num_segments (scalar)
// Output: f32 [NI=4096, 19]
// ---------------------------------------------------------------------------
extern "C" void kernel_launch(void* const* d_in, const int* in_sizes, int n_in,
                              void* d_out, int out_size) {
    const float* X    = (const float*)d_in[0];
    const float* W    = (const float*)d_in[1];
    const float* b    = (const float*)d_in[2];
    const int*   pidx = (const int*)d_in[3];
    const int*   segs = (const int*)d_in[4];
    float*       out  = (float*)d_out;

    const int P  = in_sizes[3];
    const int NI = out_size / NC;

    proj_kernel<<<NROWS / ROWS_PER_BLOCK, THREADS_GEMM>>>(X, W);
    seg_kernel<<<NI, 128>>>(pidx, segs, b, out, P);
}

// round 2
// speedup vs baseline: 1.1789x; 1.1789x over previous
#include <cuda_runtime.h>

// Problem constants (fixed shapes)
#define DIMD 272
#define NC   19
#define ZS   20            // padded Z/W column stride (even -> 8B aligned pairs)
#define NPAIR 10           // ZS/2 column pairs
#define NROWS 65536        // B*H*Wd
#define NISEG 4096
#define ROWS_PER_BLOCK 256
#define THREADS_GEMM 128
#define DCHUNK 17          // 272 = 16*17
#define NCHUNKS 16
#define XS_STRIDE 19       // odd -> conflict-free strided column reads
#define GROUPS 6           // 6*19 = 114 accumulation lanes
#define SEG_CHUNK 2048     // staged pidx chunk per block

typedef unsigned long long ull;

__device__ float g_Z[(size_t)NROWS * ZS];   // projected features, padded
__device__ int   g_off[NISEG + 1];          // segment start offsets

__device__ __forceinline__ ull pack2(float lo, float hi) {
    ull r; asm("mov.b64 %0, {%1, %2};" : "=l"(r) : "f"(lo), "f"(hi)); return r;
}
__device__ __forceinline__ void fma2(ull& d, ull a, ull b, ull c) {
    asm("fma.rn.f32x2 %0, %1, %2, %3;" : "=l"(d) : "l"(a), "l"(b), "l"(c));
}

// ---------------------------------------------------------------------------
// Kernel 1: Z[r][0:19] = X[r][:] @ W   via packed f32x2 FFMA.
// Each thread: 2 rows x 20 cols (10 f32x2 pairs per row).
// ---------------------------------------------------------------------------
__global__ __launch_bounds__(THREADS_GEMM)
void proj_kernel(const float* __restrict__ X, const float* __restrict__ W) {
    __shared__ float ws[DIMD * ZS];                   // 21760 B, padded W
    __shared__ float xs[ROWS_PER_BLOCK * XS_STRIDE]; // 19456 B

    const int t = threadIdx.x;
    const int row0 = blockIdx.x * ROWS_PER_BLOCK;

    // Stage W padded to 20 cols
    for (int i = t; i < DIMD * ZS; i += THREADS_GEMM) {
        int dd = i / ZS, c = i - dd * ZS;
        ws[i] = (c < NC) ? W[dd * NC + c] : 0.f;
    }

    ull acc0[NPAIR], acc1[NPAIR];
    const ull z2 = pack2(0.f, 0.f);
#pragma unroll
    for (int j = 0; j < NPAIR; j++) { acc0[j] = z2; acc1[j] = z2; }

    for (int ch = 0; ch < NCHUNKS; ch++) {
        __syncthreads();
        for (int i = t; i < ROWS_PER_BLOCK * DCHUNK; i += THREADS_GEMM) {
            int r  = i / DCHUNK;
            int dd = i - r * DCHUNK;
            xs[r * XS_STRIDE + dd] =
                X[(size_t)(row0 + r) * DIMD + ch * DCHUNK + dd];
        }
        __syncthreads();

        const ull* wp = (const ull*)&ws[ch * DCHUNK * ZS];
        for (int dd = 0; dd < DCHUNK; dd++) {
            float xa = xs[t * XS_STRIDE + dd];
            float xb = xs[(t + 128) * XS_STRIDE + dd];
            ull xaa = pack2(xa, xa);
            ull xbb = pack2(xb, xb);
#pragma unroll
            for (int j = 0; j < NPAIR; j++) {
                ull w = wp[dd * NPAIR + j];   // LDS.64 broadcast
                fma2(acc0[j], xaa, w, acc0[j]);
                fma2(acc1[j], xbb, w, acc1[j]);
            }
        }
    }

    ull* za = (ull*)&g_Z[(size_t)(row0 + t) * ZS];
    ull* zb = (ull*)&g_Z[(size_t)(row0 + t + 128) * ZS];
#pragma unroll
    for (int j = 0; j < NPAIR; j++) { za[j] = acc0[j]; zb[j] = acc1[j]; }
}

// ---------------------------------------------------------------------------
// Kernel 2a: segment boundary offsets (segment_ids sorted).
// ---------------------------------------------------------------------------
__global__ __launch_bounds__(256)
void bounds_kernel(const int* __restrict__ segs, int P) {
    int p = blockIdx.x * 256 + threadIdx.x;
    if (p >= P) return;
    int s    = segs[p];
    int prev = (p == 0) ? -1 : segs[p - 1];
    for (int q = prev + 1; q <= s; q++) g_off[q] = p;     // covers empty segs
    if (p == P - 1)
        for (int q = s + 1; q <= NISEG; q++) g_off[q] = P;
}

// ---------------------------------------------------------------------------
// Kernel 2b: one block per segment. Stage pidx chunk into shared, then
// 6 groups x 19 lanes accumulate Z rows with high MLP; /count + bias, sigmoid.
// ---------------------------------------------------------------------------
__global__ __launch_bounds__(128)
void seg_kernel(const int* __restrict__ pidx, const float* __restrict__ bias,
                float* __restrict__ out) {
    const int s = blockIdx.x;
    const int t = threadIdx.x;
    const int start = g_off[s];
    const int end   = g_off[s + 1];

    __shared__ int   sp[SEG_CHUNK];
    __shared__ float sAcc[GROUPS * NC];

    const int g = t / NC;          // group (0..6), group 6 = idle lanes
    const int c = t - g * NC;
    float acc = 0.f;

    for (int base = start; base < end; base += SEG_CHUNK) {
        const int n = min(end - base, SEG_CHUNK);
        for (int i = t; i < n; i += 128) sp[i] = pidx[base + i];
        __syncthreads();
        if (g < GROUPS) {
#pragma unroll 4
            for (int p = g; p < n; p += GROUPS) {
                int r = sp[p];
                acc += g_Z[(size_t)r * ZS + c];
            }
        }
        __syncthreads();
    }

    if (g < GROUPS) sAcc[t] = acc;
    __syncthreads();

    if (t < NC) {
        float sum = 0.f;
#pragma unroll
        for (int q = 0; q < GROUPS; q++) sum += sAcc[q * NC + t];
        float cnt = (float)(end - start);
        float pooled = sum / fmaxf(cnt, 1.0f);
        float x = pooled + bias[t];
        out[(size_t)s * NC + t] = 1.0f / (1.0f + __expf(-x));
    }
}

// ---------------------------------------------------------------------------
extern "C" void kernel_launch(void* const* d_in, const int* in_sizes, int n_in,
                              void* d_out, int out_size) {
    const float* X    = (const float*)d_in[0];
    const float* W    = (const float*)d_in[1];
    const float* b    = (const float*)d_in[2];
    const int*   pidx = (const int*)d_in[3];
    const int*   segs = (const int*)d_in[4];
    float*       out  = (float*)d_out;

    const int P = in_sizes[3];

    bounds_kernel<<<(P + 255) / 256, 256>>>(segs, P);
    proj_kernel<<<NROWS / ROWS_PER_BLOCK, THREADS_GEMM>>>(X, W);
    seg_kernel<<<NISEG, 128>>>(pidx, b, out);
}

// round 4
// speedup vs baseline: 1.5302x; 1.2980x over previous
#include <cuda_runtime.h>

// Fixed problem shapes
#define DIMD 272
#define NC   19
#define ZS   20            // padded Z/W column stride
#define NPAIR 10
#define NROWS 65536        // B*H*Wd
#define NISEG 4096
#define THREADS 128
#define RPT 2              // rows per thread in proj
#define PB_ROWS (THREADS * RPT)          // 256 rows per proj block
#define PROJ_BLOCKS (NROWS / PB_ROWS)    // 256
#define DCHUNK 8           // floats per prefetch chunk (32B, aligned)
#define NCHUNKS 34         // 272 / 8
#define PPT 16             // points per thread in bounds part
#define GROUPS 6           // 6*19 = 114 accumulation lanes in seg kernel
#define SEG_CHUNK 2048

typedef unsigned long long ull;

__device__ float g_Z[(size_t)NROWS * ZS];   // projected features (padded)
__device__ int   g_off[NISEG + 1];          // segment start offsets

__device__ __forceinline__ ull pack2(float lo, float hi) {
    ull r; asm("mov.b64 %0, {%1, %2};" : "=l"(r) : "f"(lo), "f"(hi)); return r;
}
__device__ __forceinline__ void fma2(ull& d, ull a, ull b) {
    asm("fma.rn.f32x2 %0, %1, %2, %0;" : "+l"(d) : "l"(a), "l"(b));
}

// Load one 8-float chunk of two rows into register arrays (2x LDG.128 each).
__device__ __forceinline__ void loadc(const float4* __restrict__ xa4,
                                      const float4* __restrict__ xb4,
                                      int ch, float* a, float* b) {
    float4 u0 = __ldg(xa4 + ch * 2), u1 = __ldg(xa4 + ch * 2 + 1);
    float4 v0 = __ldg(xb4 + ch * 2), v1 = __ldg(xb4 + ch * 2 + 1);
    a[0]=u0.x; a[1]=u0.y; a[2]=u0.z; a[3]=u0.w;
    a[4]=u1.x; a[5]=u1.y; a[6]=u1.z; a[7]=u1.w;
    b[0]=v0.x; b[1]=v0.y; b[2]=v0.z; b[3]=v0.w;
    b[4]=v1.x; b[5]=v1.y; b[6]=v1.z; b[7]=v1.w;
}

// FFMA2 one chunk: 8 dd x 10 column-pairs x 2 rows, W via LDS.128.
__device__ __forceinline__ void computec(const float* __restrict__ ws, int ch,
                                         const float* a, const float* b,
                                         ull* acc0, ull* acc1) {
    const ulonglong2* wq = (const ulonglong2*)(ws + ch * DCHUNK * ZS);
#pragma unroll
    for (int dd = 0; dd < DCHUNK; dd++) {
        ull xaa = pack2(a[dd], a[dd]);
        ull xbb = pack2(b[dd], b[dd]);
#pragma unroll
        for (int jj = 0; jj < 5; jj++) {
            ulonglong2 w = wq[dd * 5 + jj];      // LDS.128 broadcast
            fma2(acc0[2*jj],   xaa, w.x);
            fma2(acc0[2*jj+1], xaa, w.y);
            fma2(acc1[2*jj],   xbb, w.x);
            fma2(acc1[2*jj+1], xbb, w.y);
        }
    }
}

// ---------------------------------------------------------------------------
// Fat kernel: blocks [0, PROJ_BLOCKS) do Z = X@W ; remaining blocks compute
// segment boundary offsets from the sorted segment_ids. Independent work,
// overlapped in one launch.
// ---------------------------------------------------------------------------
__global__ __launch_bounds__(THREADS)
void fat_kernel(const float* __restrict__ X, const float* __restrict__ W,
                const int* __restrict__ segs, int P) {
    if (blockIdx.x < PROJ_BLOCKS) {
        // ----------------- projection part -----------------
        __shared__ __align__(16) float ws[DIMD * ZS];   // 21760 B
        const int t = threadIdx.x;
        for (int i = t; i < DIMD * ZS; i += THREADS) {
            int dd = i / ZS, c = i - dd * ZS;
            ws[i] = (c < NC) ? W[dd * NC + c] : 0.f;
        }
        __syncthreads();

        const int r0 = blockIdx.x * PB_ROWS + t;
        const int r1 = r0 + THREADS;
        const float4* xa4 = (const float4*)(X + (size_t)r0 * DIMD);
        const float4* xb4 = (const float4*)(X + (size_t)r1 * DIMD);

        ull acc0[NPAIR], acc1[NPAIR];
        const ull z2 = pack2(0.f, 0.f);
#pragma unroll
        for (int j = 0; j < NPAIR; j++) { acc0[j] = z2; acc1[j] = z2; }

        float bufAa[DCHUNK], bufAb[DCHUNK], bufBa[DCHUNK], bufBb[DCHUNK];
        loadc(xa4, xb4, 0, bufAa, bufAb);
        // ping-pong: even chunks in bufA, odd in bufB (NCHUNKS is even)
        for (int ch = 0; ch < NCHUNKS; ch += 2) {
            loadc(xa4, xb4, ch + 1, bufBa, bufBb);            // prefetch odd
            computec(ws, ch, bufAa, bufAb, acc0, acc1);
            if (ch + 2 < NCHUNKS)
                loadc(xa4, xb4, ch + 2, bufAa, bufAb);        // prefetch even
            computec(ws, ch + 1, bufBa, bufBb, acc0, acc1);
        }

        ulonglong2* za = (ulonglong2*)&g_Z[(size_t)r0 * ZS];  // 80B rows, 16B aligned
        ulonglong2* zb = (ulonglong2*)&g_Z[(size_t)r1 * ZS];
#pragma unroll
        for (int jj = 0; jj < 5; jj++) {
            ulonglong2 sa; sa.x = acc0[2*jj]; sa.y = acc0[2*jj+1];
            ulonglong2 sb; sb.x = acc1[2*jj]; sb.y = acc1[2*jj+1];
            za[jj] = sa; zb[jj] = sb;
        }
    } else {
        // ----------------- segment bounds part -----------------
        const int base = (blockIdx.x - PROJ_BLOCKS) * (THREADS * PPT)
                       + threadIdx.x * PPT;
        if (base >= P) return;
        int vv[PPT];
        const int4* s4 = (const int4*)(segs + base);
#pragma unroll
        for (int q = 0; q < PPT / 4; q++) {
            int4 v = __ldg(s4 + q);
            vv[q*4+0] = v.x; vv[q*4+1] = v.y; vv[q*4+2] = v.z; vv[q*4+3] = v.w;
        }
        int prev = (base == 0) ? -1 : __ldg(segs + base - 1);
#pragma unroll
        for (int k = 0; k < PPT; k++) {
            int s = vv[k];
            if (s != prev)
                for (int q = prev + 1; q <= s; q++) g_off[q] = base + k;
            prev = s;
        }
        if (base + PPT >= P)
            for (int q = prev + 1; q <= NISEG; q++) g_off[q] = P;
    }
}

// ---------------------------------------------------------------------------
// Seg kernel: one block per segment; stage pidx chunk in shared; 6 groups x 19
// lanes accumulate Z rows; mean + bias + sigmoid.
// ---------------------------------------------------------------------------
__global__ __launch_bounds__(128)
void seg_kernel(const int* __restrict__ pidx, const float* __restrict__ bias,
                float* __restrict__ out) {
    const int s = blockIdx.x;
    const int t = threadIdx.x;
    const int start = g_off[s];
    const int end   = g_off[s + 1];

    __shared__ int   sp[SEG_CHUNK];
    __shared__ float sAcc[GROUPS * NC];

    const int g = t / NC;
    const int c = t - g * NC;
    float acc = 0.f;

    for (int base = start; base < end; base += SEG_CHUNK) {
        const int n = min(end - base, SEG_CHUNK);
        for (int i = t; i < n; i += 128) sp[i] = pidx[base + i];
        __syncthreads();
        if (g < GROUPS) {
#pragma unroll 4
            for (int p = g; p < n; p += GROUPS) {
                int r = sp[p];
                acc += g_Z[(size_t)r * ZS + c];
            }
        }
        __syncthreads();
    }

    if (g < GROUPS) sAcc[t] = acc;
    __syncthreads();

    if (t < NC) {
        float sum = 0.f;
#pragma unroll
        for (int q = 0; q < GROUPS; q++) sum += sAcc[q * NC + t];
        float cnt = (float)(end - start);
        float pooled = sum / fmaxf(cnt, 1.0f);
        float x = pooled + bias[t];
        out[(size_t)s * NC + t] = 1.0f / (1.0f + __expf(-x));
    }
}

// ---------------------------------------------------------------------------
extern "C" void kernel_launch(void* const* d_in, const int* in_sizes, int n_in,
                              void* d_out, int out_size) {
    const float* X    = (const float*)d_in[0];
    const float* W    = (const float*)d_in[1];
    const float* b    = (const float*)d_in[2];
    const int*   pidx = (const int*)d_in[3];
    const int*   segs = (const int*)d_in[4];
    float*       out  = (float*)d_out;

    const int P = in_sizes[3];
    const int boundsBlocks = (P + THREADS * PPT - 1) / (THREADS * PPT);

    fat_kernel<<<PROJ_BLOCKS + boundsBlocks, THREADS>>>(X, W, segs, P);
    seg_kernel<<<NISEG, 128>>>(pidx, b, out);
}